// round 1
// baseline (speedup 1.0000x reference)
#include <cuda_runtime.h>

#define NBLK 152
#define TPB  256
#define B_N  4096
#define D_N  3072
#define C_N  10
#define MAXR 28

__device__ float g_M[C_N * C_N];
__device__ float g_partial[NBLK];
__device__ unsigned int g_ticket;

// ---------------- Kernel 1: M = W^T W (10x10), also resets ticket ----------------
__global__ void compute_M_kernel(const float* __restrict__ W) {
    int k = blockIdx.x;            // row of M
    int tid = threadIdx.x;
    if (k == 0 && tid == 0) g_ticket = 0u;
    float acc[C_N];
#pragma unroll
    for (int l = 0; l < C_N; l++) acc[l] = 0.f;
    for (int d = tid; d < D_N; d += TPB) {
        float wk = W[d * C_N + k];
#pragma unroll
        for (int l = 0; l < C_N; l++) acc[l] += wk * W[d * C_N + l];
    }
#pragma unroll
    for (int off = 16; off; off >>= 1)
#pragma unroll
        for (int l = 0; l < C_N; l++)
            acc[l] += __shfl_xor_sync(0xffffffffu, acc[l], off);
    __shared__ float red[8][C_N];
    int warp = tid >> 5, lane = tid & 31;
    if (lane == 0)
#pragma unroll
        for (int l = 0; l < C_N; l++) red[warp][l] = acc[l];
    __syncthreads();
    if (warp == 0 && lane < C_N) {
        float s = 0.f;
#pragma unroll
        for (int w = 0; w < 8; w++) s += red[w][lane];
        g_M[k * C_N + lane] = s;
    }
}

// ---------------- Kernel 2: everything else ----------------
__global__ void __launch_bounds__(TPB, 1) jacreg_main_kernel(
        const float* __restrict__ X, const float* __restrict__ W,
        float* __restrict__ out) {
    const int tid = threadIdx.x, b = blockIdx.x;
    const int warp = tid >> 5, lane = tid & 31;
    const int r0 = (b * B_N) / NBLK;
    const int r1 = ((b + 1) * B_N) / NBLK;
    const int nrows = r1 - r0;          // <= 27

    __shared__ float sM[C_N * C_N];
    __shared__ float sp[MAXR][8][C_N];  // per-row per-warp partial z
    __shared__ int slast;

    if (tid < C_N * C_N) sM[tid] = g_M[tid];

    // Preload this thread's 12 rows of W into registers (element e = (j*256+tid)*4+c4)
    float w[3][4][C_N];
#pragma unroll
    for (int j = 0; j < 3; j++)
#pragma unroll
        for (int c4 = 0; c4 < 4; c4++) {
            int e = (j * TPB + tid) * 4 + c4;
#pragma unroll
            for (int k = 0; k < C_N; k++) w[j][c4][k] = W[e * C_N + k];
        }

    const float4* __restrict__ X4 = (const float4*)X;
    size_t base0 = (size_t)r0 * (D_N / 4) + tid;
    float4 xn0 = X4[base0];
    float4 xn1 = X4[base0 + TPB];
    float4 xn2 = X4[base0 + 2 * TPB];

    // -------- Phase A: per-row logits (no barriers; warps fully independent) --------
    for (int rl = 0; rl < nrows; rl++) {
        float4 x0 = xn0, x1 = xn1, x2 = xn2;
        if (rl + 1 < nrows) {   // prefetch next row
            size_t nb = (size_t)(r0 + rl + 1) * (D_N / 4) + tid;
            xn0 = X4[nb];
            xn1 = X4[nb + TPB];
            xn2 = X4[nb + 2 * TPB];
        }
        float acc[C_N];
#pragma unroll
        for (int k = 0; k < C_N; k++) acc[k] = 0.f;
#pragma unroll
        for (int k = 0; k < C_N; k++) {
            acc[k] += x0.x * w[0][0][k];
            acc[k] += x0.y * w[0][1][k];
            acc[k] += x0.z * w[0][2][k];
            acc[k] += x0.w * w[0][3][k];
            acc[k] += x1.x * w[1][0][k];
            acc[k] += x1.y * w[1][1][k];
            acc[k] += x1.z * w[1][2][k];
            acc[k] += x1.w * w[1][3][k];
            acc[k] += x2.x * w[2][0][k];
            acc[k] += x2.y * w[2][1][k];
            acc[k] += x2.z * w[2][2][k];
            acc[k] += x2.w * w[2][3][k];
        }
#pragma unroll
        for (int off = 16; off; off >>= 1)
#pragma unroll
            for (int k = 0; k < C_N; k++)
                acc[k] += __shfl_xor_sync(0xffffffffu, acc[k], off);
        if (lane == 0)
#pragma unroll
            for (int k = 0; k < C_N; k++) sp[rl][warp][k] = acc[k];
    }
    __syncthreads();

    // -------- Phase B: one thread per row does all scalar math --------
    float myreg = 0.f;
    if (tid < nrows) {
        float z[C_N];
#pragma unroll
        for (int k = 0; k < C_N; k++) {
            float s = 0.f;
#pragma unroll
            for (int wv = 0; wv < 8; wv++) s += sp[tid][wv][k];
            z[k] = s;
        }
        float zmax = z[0];
#pragma unroll
        for (int k = 1; k < C_N; k++) zmax = fmaxf(zmax, z[k]);
        float q[C_N], qs = 0.f;
#pragma unroll
        for (int k = 0; k < C_N; k++) { q[k] = __expf(z[k] - zmax); qs += q[k]; }
        float inv = 1.f / qs;
#pragma unroll
        for (int k = 0; k < C_N; k++) q[k] *= inv;

        const float A = 1.0f - (float)C_N * 1e-6f;   // 1 - c*num_stab
        float p[C_N], s[C_N];
#pragma unroll
        for (int k = 0; k < C_N; k++) { p[k] = q[k] * A + 1e-6f; s[k] = sqrtf(p[k]); }
        float sm = s[C_N - 1], qm = q[C_N - 1];
        float om = 1.f - sm;

        // u = M q, Qf = q^T M q
        float u[C_N], Qf = 0.f;
#pragma unroll
        for (int k = 0; k < C_N; k++) {
            float t = 0.f;
#pragma unroll
            for (int l = 0; l < C_N; l++) t += sM[k * C_N + l] * q[l];
            u[k] = t;
            Qf += q[k] * t;
        }

        float jac2 = 0.f;
        float bfac = A * qm / (sm * om * om);
#pragma unroll
        for (int i = 0; i < C_N - 1; i++) {
            float al = A * q[i] / (s[i] * om);
            float be = s[i] * bfac;
            float ga = al + be;
            jac2 += al * al * sM[i * C_N + i]
                  + be * be * sM[C_N * C_N - 1]
                  + ga * ga * Qf
                  + 2.f * al * be * sM[i * C_N + (C_N - 1)]
                  - 2.f * al * ga * u[i]
                  - 2.f * be * ga * u[C_N - 1];
        }
        float jn = sqrtf(jac2);

        float ssum = 0.f;
#pragma unroll
        for (int k = 0; k < C_N; k++) ssum += s[k];
        float arg = ssum * 0.316227766016838f;   // 1/sqrt(10)
        arg = fminf(fmaxf(arg, -1.f), 1.f);
        float delta = 2.f * acosf(arg);

        float psum = 0.f;
#pragma unroll
        for (int k = 0; k < C_N - 1; k++) psum += p[k];
        float rho = (2.f * om - psum) / om;

        float xv = jn - delta / (rho * 0.1f);    // EPSILON = 0.1
        myreg = (xv > 0.f) ? xv : expm1f(xv);    // elu
    }

    // block reduce (rows live only in warp 0 lanes)
    if (warp == 0) {
#pragma unroll
        for (int off = 16; off; off >>= 1)
            myreg += __shfl_xor_sync(0xffffffffu, myreg, off);
        if (lane == 0) {
            g_partial[b] = myreg;
            __threadfence();
            unsigned int rank = atomicAdd(&g_ticket, 1u);
            slast = (rank == NBLK - 1) ? 1 : 0;
        }
    }
    __syncthreads();

    // last block sums all partials (deterministic lane-ordered reduction)
    if (slast && warp == 0) {
        float s = 0.f;
        for (int i = lane; i < NBLK; i += 32) s += __ldcg(&g_partial[i]);
#pragma unroll
        for (int off = 16; off; off >>= 1)
            s += __shfl_xor_sync(0xffffffffu, s, off);
        if (lane == 0) out[0] = s * (1.f / (float)B_N);
    }
}

extern "C" void kernel_launch(void* const* d_in, const int* in_sizes, int n_in,
                              void* d_out, int out_size) {
    const float* X = (const float*)d_in[0];   // data [4096, 3072]
    const float* W = (const float*)d_in[1];   // W    [3072, 10]
    float* out = (float*)d_out;
    compute_M_kernel<<<C_N, TPB>>>(W);
    jacreg_main_kernel<<<NBLK, TPB>>>(X, W, out);
}

// round 2
// speedup vs baseline: 1.0996x; 1.0996x over previous
#include <cuda_runtime.h>

#define NBLK 152
#define TPB  512
#define B_N  4096
#define D_N  3072
#define C_N  10
#define MAXR 27
#define NW   (TPB / 32)

typedef unsigned long long ull;

__device__ float g_M[C_N * C_N];
__device__ float g_partial[NBLK];
__device__ unsigned int g_ticket;

// ---------------- Kernel 1: M = W^T W (10x10), also resets ticket ----------------
__global__ void compute_M_kernel(const float* __restrict__ W) {
    int k = blockIdx.x;
    int tid = threadIdx.x;
    if (k == 0 && tid == 0) g_ticket = 0u;
    float acc[C_N];
#pragma unroll
    for (int l = 0; l < C_N; l++) acc[l] = 0.f;
    for (int d = tid; d < D_N; d += 256) {
        float wk = W[d * C_N + k];
#pragma unroll
        for (int l = 0; l < C_N; l++) acc[l] += wk * W[d * C_N + l];
    }
#pragma unroll
    for (int off = 16; off; off >>= 1)
#pragma unroll
        for (int l = 0; l < C_N; l++)
            acc[l] += __shfl_xor_sync(0xffffffffu, acc[l], off);
    __shared__ float red[8][C_N];
    int warp = tid >> 5, lane = tid & 31;
    if (lane == 0)
#pragma unroll
        for (int l = 0; l < C_N; l++) red[warp][l] = acc[l];
    __syncthreads();
    if (warp == 0 && lane < C_N) {
        float s = 0.f;
#pragma unroll
        for (int w = 0; w < 8; w++) s += red[w][lane];
        g_M[k * C_N + lane] = s;
    }
}

// ---------------- Kernel 2: everything else ----------------
__global__ void __launch_bounds__(TPB, 1) jacreg_main_kernel(
        const float* __restrict__ X, const float* __restrict__ W,
        float* __restrict__ out) {
    const int tid = threadIdx.x, b = blockIdx.x;
    const int warp = tid >> 5, lane = tid & 31;
    const int r0 = (b * B_N) / NBLK;
    const int r1 = ((b + 1) * B_N) / NBLK;
    const int nrows = r1 - r0;          // 26 or 27

    __shared__ float sM[C_N * C_N];
    __shared__ float sp[MAXR][NW][C_N];
    __shared__ int slast;

    if (tid < C_N * C_N) sM[tid] = g_M[tid];

    // W packed into f32x2 pairs: thread owns 6 D-positions: e = (j*TPB+tid)*2 + c2
    ull wp[3][2][5];
#pragma unroll
    for (int j = 0; j < 3; j++)
#pragma unroll
        for (int c2 = 0; c2 < 2; c2++) {
            int e = (j * TPB + tid) * 2 + c2;
            const ull* wrow = (const ull*)(W + (size_t)e * C_N);  // 8B aligned (stride 40B)
#pragma unroll
            for (int m = 0; m < 5; m++) wp[j][c2][m] = wrow[m];
        }

    const float2* __restrict__ X2 = (const float2*)X;
    size_t base0 = (size_t)r0 * (D_N / 2) + tid;
    float2 a0 = __ldcs(X2 + base0);
    float2 a1 = __ldcs(X2 + base0 + TPB);
    float2 a2 = __ldcs(X2 + base0 + 2 * TPB);
    float2 bb0, bb1, bb2;
    {
        size_t nb = base0 + (D_N / 2);
        bb0 = __ldcs(X2 + nb);
        bb1 = __ldcs(X2 + nb + TPB);
        bb2 = __ldcs(X2 + nb + 2 * TPB);
    }

    // -------- Phase A: per-row logits (no barriers inside; warps independent) --------
    for (int rl = 0; rl < nrows; rl++) {
        float2 x0 = a0, x1 = a1, x2 = a2;
        a0 = bb0; a1 = bb1; a2 = bb2;
        if (rl + 2 < nrows) {   // depth-2 prefetch
            size_t nb = (size_t)(r0 + rl + 2) * (D_N / 2) + tid;
            bb0 = __ldcs(X2 + nb);
            bb1 = __ldcs(X2 + nb + TPB);
            bb2 = __ldcs(X2 + nb + 2 * TPB);
        }

        ull acc[5];
#pragma unroll
        for (int m = 0; m < 5; m++) acc[m] = 0ull;

#pragma unroll
        for (int j = 0; j < 3; j++)
#pragma unroll
            for (int c2 = 0; c2 < 2; c2++) {
                float xv = (j == 0) ? (c2 == 0 ? x0.x : x0.y)
                         : (j == 1) ? (c2 == 0 ? x1.x : x1.y)
                                    : (c2 == 0 ? x2.x : x2.y);
                ull xb;
                asm("mov.b64 %0, {%1, %1};" : "=l"(xb) : "f"(xv));
#pragma unroll
                for (int m = 0; m < 5; m++)
                    asm("fma.rn.f32x2 %0, %1, %2, %0;"
                        : "+l"(acc[m]) : "l"(xb), "l"(wp[j][c2][m]));
            }

        float z[C_N];
#pragma unroll
        for (int m = 0; m < 5; m++)
            asm("mov.b64 {%0, %1}, %2;" : "=f"(z[2 * m]), "=f"(z[2 * m + 1]) : "l"(acc[m]));

        // Value-splitting reduction: 10 -> 5 (xor16), 5 -> 3 (xor8), then 3x3 naive
        const bool hi16 = (lane & 16) != 0;
        const bool hi8  = (lane & 8) != 0;
        float v[5];
#pragma unroll
        for (int j = 0; j < 5; j++) {
            float send = hi16 ? z[j] : z[j + 5];
            float oth = __shfl_xor_sync(0xffffffffu, send, 16);
            v[j] = (hi16 ? z[j + 5] : z[j]) + oth;
        }
        float u[3];
#pragma unroll
        for (int j = 0; j < 3; j++) {
            float mine = (j < 2) ? v[j + 3] : 0.f;
            float send = hi8 ? v[j] : mine;
            float oth = __shfl_xor_sync(0xffffffffu, send, 8);
            u[j] = (hi8 ? mine : v[j]) + oth;
        }
#pragma unroll
        for (int off = 4; off; off >>= 1)
#pragma unroll
            for (int j = 0; j < 3; j++)
                u[j] += __shfl_xor_sync(0xffffffffu, u[j], off);

        if ((lane & 7) == 0) {
            int vb = (hi16 ? 5 : 0) + (hi8 ? 3 : 0);
            int cnt = hi8 ? 2 : 3;
#pragma unroll
            for (int j = 0; j < 3; j++)
                if (j < cnt) sp[rl][warp][vb + j] = u[j];
        }
    }
    __syncthreads();

    // -------- Phase B: one thread per row does all scalar math --------
    float myreg = 0.f;
    if (tid < nrows) {
        float z[C_N];
#pragma unroll
        for (int k = 0; k < C_N; k++) {
            float s = 0.f;
#pragma unroll
            for (int wv = 0; wv < NW; wv++) s += sp[tid][wv][k];
            z[k] = s;
        }
        float zmax = z[0];
#pragma unroll
        for (int k = 1; k < C_N; k++) zmax = fmaxf(zmax, z[k]);
        float q[C_N], qs = 0.f;
#pragma unroll
        for (int k = 0; k < C_N; k++) { q[k] = __expf(z[k] - zmax); qs += q[k]; }
        float inv = 1.f / qs;
#pragma unroll
        for (int k = 0; k < C_N; k++) q[k] *= inv;

        const float A = 1.0f - (float)C_N * 1e-6f;
        float p[C_N], s[C_N];
#pragma unroll
        for (int k = 0; k < C_N; k++) { p[k] = q[k] * A + 1e-6f; s[k] = sqrtf(p[k]); }
        float sm = s[C_N - 1], qm = q[C_N - 1];
        float om = 1.f - sm;

        float u[C_N], Qf = 0.f;
#pragma unroll
        for (int k = 0; k < C_N; k++) {
            float t = 0.f;
#pragma unroll
            for (int l = 0; l < C_N; l++) t += sM[k * C_N + l] * q[l];
            u[k] = t;
            Qf += q[k] * t;
        }

        float jac2 = 0.f;
        float bfac = A * qm / (sm * om * om);
#pragma unroll
        for (int i = 0; i < C_N - 1; i++) {
            float al = A * q[i] / (s[i] * om);
            float be = s[i] * bfac;
            float ga = al + be;
            jac2 += al * al * sM[i * C_N + i]
                  + be * be * sM[C_N * C_N - 1]
                  + ga * ga * Qf
                  + 2.f * al * be * sM[i * C_N + (C_N - 1)]
                  - 2.f * al * ga * u[i]
                  - 2.f * be * ga * u[C_N - 1];
        }
        float jn = sqrtf(jac2);

        float ssum = 0.f;
#pragma unroll
        for (int k = 0; k < C_N; k++) ssum += s[k];
        float arg = ssum * 0.316227766016838f;
        arg = fminf(fmaxf(arg, -1.f), 1.f);
        float delta = 2.f * acosf(arg);

        float psum = 0.f;
#pragma unroll
        for (int k = 0; k < C_N - 1; k++) psum += p[k];
        float rho = (2.f * om - psum) / om;

        float xv = jn - delta / (rho * 0.1f);
        myreg = (xv > 0.f) ? xv : expm1f(xv);
    }

    if (warp == 0) {
#pragma unroll
        for (int off = 16; off; off >>= 1)
            myreg += __shfl_xor_sync(0xffffffffu, myreg, off);
        if (lane == 0) {
            g_partial[b] = myreg;
            __threadfence();
            unsigned int rank = atomicAdd(&g_ticket, 1u);
            slast = (rank == NBLK - 1) ? 1 : 0;
        }
    }
    __syncthreads();

    if (slast && warp == 0) {
        float s = 0.f;
        for (int i = lane; i < NBLK; i += 32) s += __ldcg(&g_partial[i]);
#pragma unroll
        for (int off = 16; off; off >>= 1)
            s += __shfl_xor_sync(0xffffffffu, s, off);
        if (lane == 0) out[0] = s * (1.f / (float)B_N);
    }
}

extern "C" void kernel_launch(void* const* d_in, const int* in_sizes, int n_in,
                              void* d_out, int out_size) {
    const float* X = (const float*)d_in[0];
    const float* W = (const float*)d_in[1];
    float* out = (float*)d_out;
    compute_M_kernel<<<C_N, 256>>>(W);
    jacreg_main_kernel<<<NBLK, TPB>>>(X, W, out);
}

// round 3
// speedup vs baseline: 1.1641x; 1.0587x over previous
#include <cuda_runtime.h>
#include <cstdint>

#define NBLK 152
#define TPB  512
#define B_N  4096
#define D_N  3072
#define C_N  10
#define MAXR 27
#define NW   (TPB / 32)
#define RPT  3            // rows per tile
#define STG  4            // pipeline stages
#define TILE_FLOATS (RPT * D_N)
#define TILE_BYTES_MAX (TILE_FLOATS * 4)
#define DYN_SMEM (STG * TILE_BYTES_MAX)

typedef unsigned long long ull;

__device__ float g_M[C_N * C_N];
__device__ float g_partial[NBLK];
__device__ unsigned int g_ticket;

// ---------------- Kernel 1: M = W^T W (10x10), also resets ticket ----------------
__global__ void compute_M_kernel(const float* __restrict__ W) {
    int k = blockIdx.x;
    int tid = threadIdx.x;
    if (k == 0 && tid == 0) g_ticket = 0u;
    float acc[C_N];
#pragma unroll
    for (int l = 0; l < C_N; l++) acc[l] = 0.f;
    for (int d = tid; d < D_N; d += 256) {
        float wk = W[d * C_N + k];
#pragma unroll
        for (int l = 0; l < C_N; l++) acc[l] += wk * W[d * C_N + l];
    }
#pragma unroll
    for (int off = 16; off; off >>= 1)
#pragma unroll
        for (int l = 0; l < C_N; l++)
            acc[l] += __shfl_xor_sync(0xffffffffu, acc[l], off);
    __shared__ float red[8][C_N];
    int warp = tid >> 5, lane = tid & 31;
    if (lane == 0)
#pragma unroll
        for (int l = 0; l < C_N; l++) red[warp][l] = acc[l];
    __syncthreads();
    if (warp == 0 && lane < C_N) {
        float s = 0.f;
#pragma unroll
        for (int w = 0; w < 8; w++) s += red[w][lane];
        g_M[k * C_N + lane] = s;
    }
}

__device__ __forceinline__ uint32_t smem_u32(const void* p) {
    uint32_t a;
    asm("{ .reg .u64 t; cvta.to.shared.u64 t, %1; cvt.u32.u64 %0, t; }" : "=r"(a) : "l"(p));
    return a;
}

__device__ __forceinline__ void mbar_init(uint32_t addr, uint32_t cnt) {
    asm volatile("mbarrier.init.shared.b64 [%0], %1;" :: "r"(addr), "r"(cnt) : "memory");
}
__device__ __forceinline__ void mbar_expect_tx(uint32_t addr, uint32_t bytes) {
    asm volatile("mbarrier.arrive.expect_tx.shared.b64 _, [%0], %1;" :: "r"(addr), "r"(bytes) : "memory");
}
__device__ __forceinline__ void bulk_g2s(uint32_t dst, const void* src, uint32_t bytes, uint32_t mbar) {
    asm volatile("cp.async.bulk.shared::cta.global.mbarrier::complete_tx::bytes [%0], [%1], %2, [%3];"
                 :: "r"(dst), "l"(src), "r"(bytes), "r"(mbar) : "memory");
}
__device__ __forceinline__ void mbar_wait(uint32_t addr, uint32_t parity) {
    uint32_t done;
    asm volatile(
        "{\n\t.reg .pred p;\n\t"
        "mbarrier.try_wait.parity.shared.b64 p, [%1], %2;\n\t"
        "selp.b32 %0, 1, 0, p;\n\t}"
        : "=r"(done) : "r"(addr), "r"(parity) : "memory");
    if (!done) {
        asm volatile(
            "{\n\t.reg .pred P1;\n\t"
            "WL_%=:\n\t"
            "mbarrier.try_wait.parity.shared.b64 P1, [%0], %1, 0x989680;\n\t"
            "@P1 bra.uni WD_%=;\n\t"
            "bra.uni WL_%=;\n\t"
            "WD_%=:\n\t}"
            :: "r"(addr), "r"(parity) : "memory");
    }
}

// ---------------- Kernel 2: bulk-async staged main kernel ----------------
__global__ void __launch_bounds__(TPB, 1) jacreg_main_kernel(
        const float* __restrict__ X, const float* __restrict__ W,
        float* __restrict__ out) {
    extern __shared__ float tiles[];     // STG * RPT * D_N floats
    __shared__ float sM[C_N * C_N];
    __shared__ float sp[MAXR][NW][C_N];
    __shared__ ull mbar[STG];
    __shared__ int slast;

    const int tid = threadIdx.x, b = blockIdx.x;
    const int warp = tid >> 5, lane = tid & 31;
    const int r0 = (b * B_N) / NBLK;
    const int r1 = ((b + 1) * B_N) / NBLK;
    const int nrows = r1 - r0;                   // 26 or 27
    const int ntiles = (nrows + RPT - 1) / RPT;  // 9

    if (tid < C_N * C_N) sM[tid] = g_M[tid];

    // W packed into f32x2 pairs: thread owns 6 D-positions: e = (j*TPB+tid)*2 + c2
    ull wp[3][2][5];
#pragma unroll
    for (int j = 0; j < 3; j++)
#pragma unroll
        for (int c2 = 0; c2 < 2; c2++) {
            int e = (j * TPB + tid) * 2 + c2;
            const ull* wrow = (const ull*)(W + (size_t)e * C_N);
#pragma unroll
            for (int m = 0; m < 5; m++) wp[j][c2][m] = wrow[m];
        }

    uint32_t mbar_a = smem_u32(&mbar[0]);
    uint32_t tile_a = smem_u32(&tiles[0]);

    if (tid == 0) {
#pragma unroll
        for (int s = 0; s < STG; s++) mbar_init(mbar_a + 8 * s, 1);
        asm volatile("fence.proxy.async.shared::cta;" ::: "memory");
    }
    __syncthreads();

    // Prologue: fill all stages
    if (tid == 0) {
        int np = (ntiles < STG) ? ntiles : STG;
        for (int t = 0; t < np; t++) {
            int rbase = t * RPT;
            int cnt = nrows - rbase; if (cnt > RPT) cnt = RPT;
            uint32_t bytes = (uint32_t)cnt * D_N * 4;
            mbar_expect_tx(mbar_a + 8 * t, bytes);
            bulk_g2s(tile_a + t * TILE_BYTES_MAX,
                     X + (size_t)(r0 + rbase) * D_N, bytes, mbar_a + 8 * t);
        }
    }

    // -------- Phase A over tiles --------
    for (int t = 0; t < ntiles; t++) {
        int s = t & (STG - 1);
        uint32_t parity = (t / STG) & 1;
        mbar_wait(mbar_a + 8 * s, parity);

        int rbase = t * RPT;
        int cnt = nrows - rbase; if (cnt > RPT) cnt = RPT;
        const float2* tp = (const float2*)(tiles + s * TILE_FLOATS);

        for (int rl = 0; rl < cnt; rl++) {
            const float2* row = tp + rl * (D_N / 2);
            float2 x0 = row[tid];
            float2 x1 = row[tid + TPB];
            float2 x2 = row[tid + 2 * TPB];

            ull acc[5];
#pragma unroll
            for (int m = 0; m < 5; m++) acc[m] = 0ull;
#pragma unroll
            for (int j = 0; j < 3; j++)
#pragma unroll
                for (int c2 = 0; c2 < 2; c2++) {
                    float xv = (j == 0) ? (c2 == 0 ? x0.x : x0.y)
                             : (j == 1) ? (c2 == 0 ? x1.x : x1.y)
                                        : (c2 == 0 ? x2.x : x2.y);
                    ull xb;
                    asm("mov.b64 %0, {%1, %1};" : "=l"(xb) : "f"(xv));
#pragma unroll
                    for (int m = 0; m < 5; m++)
                        asm("fma.rn.f32x2 %0, %1, %2, %0;"
                            : "+l"(acc[m]) : "l"(xb), "l"(wp[j][c2][m]));
                }

            float z[C_N];
#pragma unroll
            for (int m = 0; m < 5; m++)
                asm("mov.b64 {%0, %1}, %2;" : "=f"(z[2*m]), "=f"(z[2*m+1]) : "l"(acc[m]));

            // Value-splitting reduction: 10 -> 5 (xor16), 5 -> 3 (xor8), then 3x3 naive
            const bool hi16 = (lane & 16) != 0;
            const bool hi8  = (lane & 8) != 0;
            float v[5];
#pragma unroll
            for (int j = 0; j < 5; j++) {
                float send = hi16 ? z[j] : z[j + 5];
                float oth = __shfl_xor_sync(0xffffffffu, send, 16);
                v[j] = (hi16 ? z[j + 5] : z[j]) + oth;
            }
            float u[3];
#pragma unroll
            for (int j = 0; j < 3; j++) {
                float mine = (j < 2) ? v[j + 3] : 0.f;
                float send = hi8 ? v[j] : mine;
                float oth = __shfl_xor_sync(0xffffffffu, send, 8);
                u[j] = (hi8 ? mine : v[j]) + oth;
            }
#pragma unroll
            for (int off = 4; off; off >>= 1)
#pragma unroll
                for (int j = 0; j < 3; j++)
                    u[j] += __shfl_xor_sync(0xffffffffu, u[j], off);

            if ((lane & 7) == 0) {
                int vb = (hi16 ? 5 : 0) + (hi8 ? 3 : 0);
                int c = hi8 ? 2 : 3;
#pragma unroll
                for (int j = 0; j < 3; j++)
                    if (j < c) sp[rbase + rl][warp][vb + j] = u[j];
            }
        }
        __syncthreads();   // all reads of stage s done

        if (tid == 0) {
            int tt = t + STG;
            if (tt < ntiles) {
                int rb = tt * RPT;
                int c = nrows - rb; if (c > RPT) c = RPT;
                uint32_t bytes = (uint32_t)c * D_N * 4;
                mbar_expect_tx(mbar_a + 8 * s, bytes);
                bulk_g2s(tile_a + s * TILE_BYTES_MAX,
                         X + (size_t)(r0 + rb) * D_N, bytes, mbar_a + 8 * s);
            }
        }
    }

    // -------- Phase B: one thread per row --------
    float myreg = 0.f;
    if (tid < nrows) {
        float z[C_N];
#pragma unroll
        for (int k = 0; k < C_N; k++) {
            float s = 0.f;
#pragma unroll
            for (int wv = 0; wv < NW; wv++) s += sp[tid][wv][k];
            z[k] = s;
        }
        float zmax = z[0];
#pragma unroll
        for (int k = 1; k < C_N; k++) zmax = fmaxf(zmax, z[k]);
        float q[C_N], qs = 0.f;
#pragma unroll
        for (int k = 0; k < C_N; k++) { q[k] = __expf(z[k] - zmax); qs += q[k]; }
        float inv = 1.f / qs;
#pragma unroll
        for (int k = 0; k < C_N; k++) q[k] *= inv;

        const float A = 1.0f - (float)C_N * 1e-6f;
        float p[C_N], sq[C_N];
#pragma unroll
        for (int k = 0; k < C_N; k++) { p[k] = q[k] * A + 1e-6f; sq[k] = sqrtf(p[k]); }
        float sm = sq[C_N - 1], qm = q[C_N - 1];
        float om = 1.f - sm;

        float uu[C_N], Qf = 0.f;
#pragma unroll
        for (int k = 0; k < C_N; k++) {
            float t = 0.f;
#pragma unroll
            for (int l = 0; l < C_N; l++) t += sM[k * C_N + l] * q[l];
            uu[k] = t;
            Qf += q[k] * t;
        }

        float jac2 = 0.f;
        float bfac = A * qm / (sm * om * om);
#pragma unroll
        for (int i = 0; i < C_N - 1; i++) {
            float al = A * q[i] / (sq[i] * om);
            float be = sq[i] * bfac;
            float ga = al + be;
            jac2 += al * al * sM[i * C_N + i]
                  + be * be * sM[C_N * C_N - 1]
                  + ga * ga * Qf
                  + 2.f * al * be * sM[i * C_N + (C_N - 1)]
                  - 2.f * al * ga * uu[i]
                  - 2.f * be * ga * uu[C_N - 1];
        }
        float jn = sqrtf(jac2);

        float ssum = 0.f;
#pragma unroll
        for (int k = 0; k < C_N; k++) ssum += sq[k];
        float arg = ssum * 0.316227766016838f;
        arg = fminf(fmaxf(arg, -1.f), 1.f);
        float delta = 2.f * acosf(arg);

        float psum = 0.f;
#pragma unroll
        for (int k = 0; k < C_N - 1; k++) psum += p[k];
        float rho = (2.f * om - psum) / om;

        float xv = jn - delta / (rho * 0.1f);
        myreg = (xv > 0.f) ? xv : expm1f(xv);
    }

    if (warp == 0) {
#pragma unroll
        for (int off = 16; off; off >>= 1)
            myreg += __shfl_xor_sync(0xffffffffu, myreg, off);
        if (lane == 0) {
            g_partial[b] = myreg;
            __threadfence();
            unsigned int rank = atomicAdd(&g_ticket, 1u);
            slast = (rank == NBLK - 1) ? 1 : 0;
        }
    }
    __syncthreads();

    if (slast && warp == 0) {
        float s = 0.f;
        for (int i = lane; i < NBLK; i += 32) s += __ldcg(&g_partial[i]);
#pragma unroll
        for (int off = 16; off; off >>= 1)
            s += __shfl_xor_sync(0xffffffffu, s, off);
        if (lane == 0) out[0] = s * (1.f / (float)B_N);
    }
}

extern "C" void kernel_launch(void* const* d_in, const int* in_sizes, int n_in,
                              void* d_out, int out_size) {
    const float* X = (const float*)d_in[0];
    const float* W = (const float*)d_in[1];
    float* out = (float*)d_out;
    cudaFuncSetAttribute(jacreg_main_kernel,
                         cudaFuncAttributeMaxDynamicSharedMemorySize, DYN_SMEM);
    compute_M_kernel<<<C_N, 256>>>(W);
    jacreg_main_kernel<<<NBLK, TPB, DYN_SMEM>>>(X, W, out);
}

// round 4
// speedup vs baseline: 1.3523x; 1.1616x over previous
#include <cuda_runtime.h>
#include <cstdint>

#define NBLK 152
#define TPB  512
#define B_N  4096
#define D_N  3072
#define C_N  10
#define MAXR 27
#define NW   (TPB / 32)
#define RPT  3
#define STG  4
#define TILE_FLOATS (RPT * D_N)
#define TILE_BYTES  (TILE_FLOATS * 4)
#define DYN_SMEM    (STG * TILE_BYTES)
#define R0BLK 23
#define REMROWS (B_N - R0BLK)
#define NB1 (NBLK - 1)

typedef unsigned long long ull;

__device__ float g_M[C_N * C_N];
__device__ float g_partial[NBLK];
__device__ unsigned int g_ticket;
__device__ unsigned int g_mflag;

__device__ __forceinline__ uint32_t smem_u32(const void* p) {
    uint32_t a;
    asm("{ .reg .u64 t; cvta.to.shared.u64 t, %1; cvt.u32.u64 %0, t; }" : "=r"(a) : "l"(p));
    return a;
}
__device__ __forceinline__ void mbar_init(uint32_t addr, uint32_t cnt) {
    asm volatile("mbarrier.init.shared.b64 [%0], %1;" :: "r"(addr), "r"(cnt) : "memory");
}
__device__ __forceinline__ void mbar_expect_tx(uint32_t addr, uint32_t bytes) {
    asm volatile("mbarrier.arrive.expect_tx.shared.b64 _, [%0], %1;" :: "r"(addr), "r"(bytes) : "memory");
}
__device__ __forceinline__ void bulk_g2s(uint32_t dst, const void* src, uint32_t bytes, uint32_t mbar) {
    asm volatile("cp.async.bulk.shared::cta.global.mbarrier::complete_tx::bytes [%0], [%1], %2, [%3];"
                 :: "r"(dst), "l"(src), "r"(bytes), "r"(mbar) : "memory");
}
__device__ __forceinline__ void mbar_wait(uint32_t addr, uint32_t parity) {
    uint32_t done;
    asm volatile(
        "{\n\t.reg .pred p;\n\t"
        "mbarrier.try_wait.parity.shared.b64 p, [%1], %2;\n\t"
        "selp.b32 %0, 1, 0, p;\n\t}"
        : "=r"(done) : "r"(addr), "r"(parity) : "memory");
    if (!done) {
        asm volatile(
            "{\n\t.reg .pred P1;\n\t"
            "WL_%=:\n\t"
            "mbarrier.try_wait.parity.shared.b64 P1, [%0], %1, 0x989680;\n\t"
            "@P1 bra.uni WD_%=;\n\t"
            "bra.uni WL_%=;\n\t"
            "WD_%=:\n\t}"
            :: "r"(addr), "r"(parity) : "memory");
    }
}

// Batched row processing: CNT rows' FMA + interleaved shuffle-reduction chains.
template<int CNT>
__device__ __forceinline__ void do_rows(const float* tile, int tid, int warp, int lane,
                                        const ull (&wp)[3][2][5],
                                        float (*sp)[NW][C_N], int rbase) {
    const float2* tp = (const float2*)tile;
    float2 x[CNT][3];
#pragma unroll
    for (int rl = 0; rl < CNT; rl++) {
        const float2* row = tp + rl * (D_N / 2);
        x[rl][0] = row[tid];
        x[rl][1] = row[tid + TPB];
        x[rl][2] = row[tid + 2 * TPB];
    }
    ull acc[CNT][5];
#pragma unroll
    for (int rl = 0; rl < CNT; rl++)
#pragma unroll
        for (int m = 0; m < 5; m++) acc[rl][m] = 0ull;

#pragma unroll
    for (int j = 0; j < 3; j++)
#pragma unroll
        for (int c2 = 0; c2 < 2; c2++)
#pragma unroll
            for (int rl = 0; rl < CNT; rl++) {
                float xv = (c2 == 0) ? x[rl][j].x : x[rl][j].y;
                ull xb;
                asm("mov.b64 %0, {%1, %1};" : "=l"(xb) : "f"(xv));
#pragma unroll
                for (int m = 0; m < 5; m++)
                    asm("fma.rn.f32x2 %0, %1, %2, %0;"
                        : "+l"(acc[rl][m]) : "l"(xb), "l"(wp[j][c2][m]));
            }

    float z[CNT][C_N];
#pragma unroll
    for (int rl = 0; rl < CNT; rl++)
#pragma unroll
        for (int m = 0; m < 5; m++)
            asm("mov.b64 {%0, %1}, %2;"
                : "=f"(z[rl][2 * m]), "=f"(z[rl][2 * m + 1]) : "l"(acc[rl][m]));

    const bool hi16 = (lane & 16) != 0;
    const bool hi8  = (lane & 8) != 0;
    float v[CNT][5];
#pragma unroll
    for (int rl = 0; rl < CNT; rl++)
#pragma unroll
        for (int j = 0; j < 5; j++) {
            float send = hi16 ? z[rl][j] : z[rl][j + 5];
            float oth = __shfl_xor_sync(0xffffffffu, send, 16);
            v[rl][j] = (hi16 ? z[rl][j + 5] : z[rl][j]) + oth;
        }
    float u[CNT][3];
#pragma unroll
    for (int rl = 0; rl < CNT; rl++)
#pragma unroll
        for (int j = 0; j < 3; j++) {
            float mine = (j < 2) ? v[rl][j + 3] : 0.f;
            float send = hi8 ? v[rl][j] : mine;
            float oth = __shfl_xor_sync(0xffffffffu, send, 8);
            u[rl][j] = (hi8 ? mine : v[rl][j]) + oth;
        }
#pragma unroll
    for (int off = 4; off; off >>= 1)
#pragma unroll
        for (int rl = 0; rl < CNT; rl++)
#pragma unroll
            for (int j = 0; j < 3; j++)
                u[rl][j] += __shfl_xor_sync(0xffffffffu, u[rl][j], off);

    if ((lane & 7) == 0) {
        int vb = (hi16 ? 5 : 0) + (hi8 ? 3 : 0);
        int c = hi8 ? 2 : 3;
#pragma unroll
        for (int rl = 0; rl < CNT; rl++)
#pragma unroll
            for (int j = 0; j < 3; j++)
                if (j < c) sp[rbase + rl][warp][vb + j] = u[rl][j];
    }
}

__global__ void __launch_bounds__(TPB, 1) jacreg_kernel(
        const float* __restrict__ X, const float* __restrict__ W,
        float* __restrict__ out) {
    extern __shared__ float tiles[];
    __shared__ float sM[C_N * C_N];
    __shared__ float sp[MAXR][NW][C_N];
    __shared__ float redM[NW][56];
    __shared__ ull mbar[STG];
    __shared__ int slast;

    const int tid = threadIdx.x, b = blockIdx.x;
    const int warp = tid >> 5, lane = tid & 31;
    int r0, r1;
    if (b == 0) { r0 = 0; r1 = R0BLK; }
    else {
        r0 = R0BLK + (int)(((long long)(b - 1) * REMROWS) / NB1);
        r1 = R0BLK + (int)(((long long)b * REMROWS) / NB1);
    }
    const int nrows = r1 - r0;                    // <= 27
    const int ntiles = (nrows + RPT - 1) / RPT;

    // W packed into f32x2 pairs: thread owns 6 D-positions
    ull wp[3][2][5];
#pragma unroll
    for (int j = 0; j < 3; j++)
#pragma unroll
        for (int c2 = 0; c2 < 2; c2++) {
            int e = (j * TPB + tid) * 2 + c2;
            const ull* wrow = (const ull*)(W + (size_t)e * C_N);
#pragma unroll
            for (int m = 0; m < 5; m++) wp[j][c2][m] = wrow[m];
        }

    uint32_t mbar_a = smem_u32(&mbar[0]);
    uint32_t tile_a = smem_u32(&tiles[0]);

    if (tid == 0) {
#pragma unroll
        for (int s = 0; s < STG; s++) mbar_init(mbar_a + 8 * s, 1);
        asm volatile("fence.proxy.async.shared::cta;" ::: "memory");
    }
    __syncthreads();

    // Prologue: fill stages (async, overlaps block0's M computation)
    if (tid == 0) {
        int np = (ntiles < STG) ? ntiles : STG;
        for (int t = 0; t < np; t++) {
            int rbase = t * RPT;
            int cnt = nrows - rbase; if (cnt > RPT) cnt = RPT;
            uint32_t bytes = (uint32_t)cnt * D_N * 4;
            mbar_expect_tx(mbar_a + 8 * t, bytes);
            bulk_g2s(tile_a + t * TILE_BYTES,
                     X + (size_t)(r0 + rbase) * D_N, bytes, mbar_a + 8 * t);
        }
    }

    // Block 0: compute M = W^T W from wp registers, publish with release flag
    if (b == 0) {
        float w[6][C_N];
#pragma unroll
        for (int j = 0; j < 3; j++)
#pragma unroll
            for (int c2 = 0; c2 < 2; c2++)
#pragma unroll
                for (int m = 0; m < 5; m++)
                    asm("mov.b64 {%0, %1}, %2;"
                        : "=f"(w[j * 2 + c2][2 * m]), "=f"(w[j * 2 + c2][2 * m + 1])
                        : "l"(wp[j][c2][m]));
        int idx = 0;
#pragma unroll
        for (int k = 0; k < C_N; k++) {
            float a[C_N];
#pragma unroll
            for (int l = k; l < C_N; l++) {
                float s = 0.f;
#pragma unroll
                for (int pos = 0; pos < 6; pos++) s += w[pos][k] * w[pos][l];
                a[l - k] = s;
            }
#pragma unroll
            for (int off = 16; off; off >>= 1)
#pragma unroll
                for (int t = 0; t < C_N - k; t++)
                    a[t] += __shfl_xor_sync(0xffffffffu, a[t], off);
            if (lane == 0)
#pragma unroll
                for (int t = 0; t < C_N - k; t++) redM[warp][idx + t] = a[t];
            idx += C_N - k;
        }
        __syncthreads();
        if (tid < 55) {
            float s = 0.f;
#pragma unroll
            for (int wv = 0; wv < NW; wv++) s += redM[wv][tid];
            int k = 0, t = tid;
            while (t >= C_N - k) { t -= C_N - k; k++; }
            int l = k + t;
            g_M[k * C_N + l] = s;
            g_M[l * C_N + k] = s;
        }
        __syncthreads();
        if (tid == 0) {
            __threadfence();
            *(volatile unsigned int*)&g_mflag = 1u;
        }
    }

    // -------- Phase A: tiles, batched rows --------
    for (int t = 0; t < ntiles; t++) {
        int s = t & (STG - 1);
        uint32_t parity = (t / STG) & 1;
        mbar_wait(mbar_a + 8 * s, parity);

        int rbase = t * RPT;
        int cnt = nrows - rbase; if (cnt > RPT) cnt = RPT;
        const float* tile = tiles + s * TILE_FLOATS;

        if (cnt == 3)      do_rows<3>(tile, tid, warp, lane, wp, sp, rbase);
        else if (cnt == 2) do_rows<2>(tile, tid, warp, lane, wp, sp, rbase);
        else               do_rows<1>(tile, tid, warp, lane, wp, sp, rbase);

        __syncthreads();   // all reads of stage s done

        if (tid == 0) {
            int tt = t + STG;
            if (tt < ntiles) {
                int rb = tt * RPT;
                int c = nrows - rb; if (c > RPT) c = RPT;
                uint32_t bytes = (uint32_t)c * D_N * 4;
                mbar_expect_tx(mbar_a + 8 * s, bytes);
                bulk_g2s(tile_a + s * TILE_BYTES,
                         X + (size_t)(r0 + rb) * D_N, bytes, mbar_a + 8 * s);
            }
        }
    }

    // Acquire M (never actually spins: block0 publishes in ~2us, Phase A takes far longer)
    if (tid == 0) {
        volatile unsigned int* vf = &g_mflag;
        while (*vf == 0u) {}
        __threadfence();
    }
    __syncthreads();
    if (tid < C_N * C_N) sM[tid] = g_M[tid];
    __syncthreads();

    // -------- Phase B: one thread per row --------
    float myreg = 0.f;
    if (tid < nrows) {
        float z[C_N];
#pragma unroll
        for (int k = 0; k < C_N; k++) {
            float s = 0.f;
#pragma unroll
            for (int wv = 0; wv < NW; wv++) s += sp[tid][wv][k];
            z[k] = s;
        }
        float zmax = z[0];
#pragma unroll
        for (int k = 1; k < C_N; k++) zmax = fmaxf(zmax, z[k]);
        float q[C_N], qs = 0.f;
#pragma unroll
        for (int k = 0; k < C_N; k++) { q[k] = __expf(z[k] - zmax); qs += q[k]; }
        float inv = 1.f / qs;
#pragma unroll
        for (int k = 0; k < C_N; k++) q[k] *= inv;

        const float A = 1.0f - (float)C_N * 1e-6f;
        float p[C_N], sq[C_N];
#pragma unroll
        for (int k = 0; k < C_N; k++) { p[k] = q[k] * A + 1e-6f; sq[k] = sqrtf(p[k]); }
        float sm = sq[C_N - 1], qm = q[C_N - 1];
        float om = 1.f - sm;

        float uu[C_N], Qf = 0.f;
#pragma unroll
        for (int k = 0; k < C_N; k++) {
            float t = 0.f;
#pragma unroll
            for (int l = 0; l < C_N; l++) t += sM[k * C_N + l] * q[l];
            uu[k] = t;
            Qf += q[k] * t;
        }

        float jac2 = 0.f;
        float bfac = A * qm / (sm * om * om);
#pragma unroll
        for (int i = 0; i < C_N - 1; i++) {
            float al = A * q[i] / (sq[i] * om);
            float be = sq[i] * bfac;
            float ga = al + be;
            jac2 += al * al * sM[i * C_N + i]
                  + be * be * sM[C_N * C_N - 1]
                  + ga * ga * Qf
                  + 2.f * al * be * sM[i * C_N + (C_N - 1)]
                  - 2.f * al * ga * uu[i]
                  - 2.f * be * ga * uu[C_N - 1];
        }
        float jn = sqrtf(jac2);

        float ssum = 0.f;
#pragma unroll
        for (int k = 0; k < C_N; k++) ssum += sq[k];
        float arg = ssum * 0.316227766016838f;
        arg = fminf(fmaxf(arg, -1.f), 1.f);
        float delta = 2.f * acosf(arg);

        float psum = 0.f;
#pragma unroll
        for (int k = 0; k < C_N - 1; k++) psum += p[k];
        float rho = (2.f * om - psum) / om;

        float xv = jn - delta / (rho * 0.1f);
        myreg = (xv > 0.f) ? xv : expm1f(xv);
    }

    if (warp == 0) {
#pragma unroll
        for (int off = 16; off; off >>= 1)
            myreg += __shfl_xor_sync(0xffffffffu, myreg, off);
        if (lane == 0) {
            g_partial[b] = myreg;
            __threadfence();
            unsigned int rank = atomicAdd(&g_ticket, 1u);
            slast = (rank == NBLK - 1) ? 1 : 0;
            if (rank == NBLK - 1) {      // reset for next graph replay
                g_ticket = 0u;
                g_mflag = 0u;
            }
        }
    }
    __syncthreads();

    if (slast && warp == 0) {
        float s = 0.f;
        for (int i = lane; i < NBLK; i += 32) s += __ldcg(&g_partial[i]);
#pragma unroll
        for (int off = 16; off; off >>= 1)
            s += __shfl_xor_sync(0xffffffffu, s, off);
        if (lane == 0) out[0] = s * (1.f / (float)B_N);
    }
}

extern "C" void kernel_launch(void* const* d_in, const int* in_sizes, int n_in,
                              void* d_out, int out_size) {
    const float* X = (const float*)d_in[0];
    const float* W = (const float*)d_in[1];
    float* out = (float*)d_out;
    cudaFuncSetAttribute(jacreg_kernel,
                         cudaFuncAttributeMaxDynamicSharedMemorySize, DYN_SMEM);
    jacreg_kernel<<<NBLK, TPB, DYN_SMEM>>>(X, W, out);
}